// round 9
// baseline (speedup 1.0000x reference)
#include <cuda_runtime.h>

// Problem constants (fixed by the dataset: H=W=128, C=100).
#define HH 128
#define WW 128
#define CC 100          // channels; CC % 4 == 0 so float4 loads stay 16B-aligned
#define TY 8            // tile rows per CTA
#define TX 8            // tile cols per CTA
#define MDMAX 15        // fast path supports max_distance <= 15
#define PWS (TX + 2*MDMAX)   // 38: padded halo stride (sized for MDMAX)
#define MAXOBJ 4        // fast path supports n_obj <= 4 (dataset has 3)
#define NTHREADS 256    // 64 pixels * 4 dy-chunk threads

__device__ __forceinline__ float dist4(float4 q, float4 p, float d) {
    float t0 = q.x - p.x, t1 = q.y - p.y, t2 = q.z - p.z, t3 = q.w - p.w;
    d = fmaf(t0, t0, d);
    d = fmaf(t1, t1, d);
    d = fmaf(t2, t2, d);
    d = fmaf(t3, t3, d);
    return d;
}

__global__ __launch_bounds__(NTHREADS)
void IntVOS_27015344292341_kernel(const float* __restrict__ prev,
                                  const float* __restrict__ query,
                                  const int*   __restrict__ labels,
                                  const int*   __restrict__ gt,
                                  const int*   __restrict__ mdp,
                                  float*       __restrict__ out,
                                  int nobj)
{
    const int md = mdp ? mdp[0] : MDMAX;
    const int K  = 2 * md + 1;

    const int tid   = threadIdx.x;
    const int tileX = blockIdx.x * TX;
    const int tileY = blockIdx.y * TY;
    const int lane  = tid & 31;
    const unsigned grpmask = 0xFu << (lane & ~3);   // the 4 lanes of this pixel

    const int pix   = tid >> 2;          // 0..63 pixel within tile
    const int chunk = tid & 3;           // dy-range chunk 0..3
    const int py = pix / TX, px = pix - (pix / TX) * TX;
    const int gy = tileY + py, gx = tileX + px;
    const float* qp = query + (gy * WW + gx) * CC;

    const int dy0 = (chunk * K) >> 2;
    const int dy1 = ((chunk + 1) * K) >> 2;

    if (md <= MDMAX && nobj <= MAXOBJ) {
        // ---------------- fast path ----------------
        __shared__ float4        smA[PWS * PWS];   // channels 0..3
        __shared__ float4        smB[PWS * PWS];   // channels 4..7
        __shared__ unsigned char smObj[PWS * PWS]; // matched object id or 255
        __shared__ int           sgt[MAXOBJ];

        if (tid < MAXOBJ) sgt[tid] = (tid < nobj) ? gt[tid] : 0;
        __syncthreads();

        // Load halo: object index + first 8 channels of prev embedding.
        const int PW = TX + 2 * md;
        for (int i = tid; i < PW * PW; i += NTHREADS) {
            const int sy = i / PW, sx = i - sy * PW;
            const int hy = tileY + sy - md, hx = tileX + sx - md;
            int o = 255;
            float4 a = make_float4(0.f, 0.f, 0.f, 0.f), b = a;
            if (hy >= 0 && hy < HH && hx >= 0 && hx < WW) {
                const int lab = labels[hy * WW + hx];
                #pragma unroll
                for (int t = 0; t < MAXOBJ; t++)
                    if (t < nobj && sgt[t] == lab) o = t;
                const float4* pp = (const float4*)(prev + (hy * WW + hx) * CC);
                a = pp[0];
                b = pp[1];
            }
            const int si = sy * PWS + sx;
            smA[si] = a;
            smB[si] = b;
            smObj[si] = (unsigned char)o;
        }
        __syncthreads();

        const float4 qa = ((const float4*)qp)[0];
        const float4 qb = ((const float4*)qp)[1];

        float best[MAXOBJ];
        #pragma unroll
        for (int t = 0; t < MAXOBJ; t++) best[t] = 1.0f;  // clamp folded into init
        int u = -1;     // the single object seen so far (for all-match detection)
        int allm = 1;   // window entirely matches one object?

        for (int dy = dy0; dy < dy1; ++dy) {
            const int base = (py + dy) * PWS + px;
            const float* prow = prev + ((gy + dy - md) * WW + (gx - md)) * CC;
            for (int dx = 0; dx < K; ++dx) {
                const int o = (int)smObj[base + dx];
                if (o == 255) { allm = 0; continue; }      // OOB or label matches no gt id
                if (u < 0) u = o; else if (o != u) allm = 0;

                float b = 1.0f;
                #pragma unroll
                for (int t = 0; t < MAXOBJ; t++) if (o == t) b = best[t];

                // Stage 1: channels 0..3 from shared. Partial sums are monotone
                // (non-negative fp32 adds), so partial >= b  =>  full d >= b: exact skip.
                float d = dist4(qa, smA[base + dx], 0.0f);
                if (d < b) {
                    // Stage 2: channels 4..7 from shared.
                    d = dist4(qb, smB[base + dx], d);
                    if (d < b) {
                        // Rare tail: channels 8..99 from global (L2-resident).
                        const float* pg = prow + dx * CC;
                        #pragma unroll 1
                        for (int c = 8; c < CC; c += 4) {
                            const float4 pv = __ldg((const float4*)(pg + c));
                            const float4 qv = __ldg((const float4*)(qp + c));
                            d = dist4(qv, pv, d);
                            if (d >= b) break;
                        }
                        if (d < b) {
                            #pragma unroll
                            for (int t = 0; t < MAXOBJ; t++) if (o == t) best[t] = d;
                        }
                    }
                }
            }
        }

        // Combine the 4 dy-chunk lanes of this pixel (all lanes converged here).
        #pragma unroll
        for (int t = 0; t < MAXOBJ; t++) {
            best[t] = fminf(best[t], __shfl_xor_sync(0xffffffffu, best[t], 1));
            best[t] = fminf(best[t], __shfl_xor_sync(0xffffffffu, best[t], 2));
        }
        {
            int am2 = __shfl_xor_sync(0xffffffffu, allm, 1);
            int u2  = __shfl_xor_sync(0xffffffffu, u, 1);
            allm = allm & am2 & ((u < 0 || u2 < 0 || u == u2) ? 1 : 0);
            u = (u < 0) ? u2 : u;
            am2 = __shfl_xor_sync(0xffffffffu, allm, 2);
            u2  = __shfl_xor_sync(0xffffffffu, u, 2);
            allm = allm & am2 & ((u < 0 || u2 < 0 || u == u2) ? 1 : 0);
            u = (u < 0) ? u2 : u;
        }

        if (allm && u >= 0) {
            // Every offset in the window matched object u: the reference takes the
            // UNCLAMPED min over full distances. Recompute exactly (extremely rare).
            float m = 3.402823466e38f;
            for (int dy = dy0; dy < dy1; ++dy) {
                for (int dx = 0; dx < K; ++dx) {
                    const float* pg = prev + ((gy + dy - md) * WW + (gx + dx - md)) * CC;
                    float d = 0.0f;
                    #pragma unroll 1
                    for (int c = 0; c < CC; c += 4) {
                        const float4 pv = __ldg((const float4*)(pg + c));
                        const float4 qv = __ldg((const float4*)(qp + c));
                        d = dist4(qv, pv, d);
                        if (d >= m) break;   // exact: partial >= m => full >= m
                    }
                    if (d < m) m = d;
                }
            }
            m = fminf(m, __shfl_xor_sync(grpmask, m, 1));
            m = fminf(m, __shfl_xor_sync(grpmask, m, 2));
            #pragma unroll
            for (int t = 0; t < MAXOBJ; t++) if (u == t) best[t] = m;
        }

        if (chunk == 0) {
            float* op = out + (gy * WW + gx) * nobj;
            #pragma unroll
            for (int t = 0; t < MAXOBJ; t++)
                if (t < nobj) op[t] = best[t];
        }
    } else {
        // ---------------- generic fallback (md > 15 or nobj > 4) ----------------
        if (chunk != 0) return;           // one thread per pixel; perf irrelevant
        const int NB = 32;
        float best[NB];
        const int no = (nobj < NB) ? nobj : NB;
        for (int t = 0; t < no; t++) best[t] = 1.0f;
        int u = -1, allm = 1;

        for (int dy = 0; dy < K; ++dy) {
            for (int dx = 0; dx < K; ++dx) {
                const int ny = gy + dy - md, nx = gx + dx - md;
                if (ny < 0 || ny >= HH || nx < 0 || nx >= WW) { allm = 0; continue; }
                const int lab = labels[ny * WW + nx];
                int o = -1;
                for (int t = 0; t < no; t++) if (__ldg(gt + t) == lab) o = t;
                if (o < 0) { allm = 0; continue; }
                if (u < 0) u = o; else if (o != u) allm = 0;
                const float b = best[o];
                const float* pg = prev + (ny * WW + nx) * CC;
                float d = 0.0f;
                for (int c = 0; c < CC; c += 4) {
                    const float4 pv = __ldg((const float4*)(pg + c));
                    const float4 qv = __ldg((const float4*)(qp + c));
                    d = dist4(qv, pv, d);
                    if (d >= b) break;
                }
                if (d < b) best[o] = d;
            }
        }
        if (allm && u >= 0) {
            float m = 3.402823466e38f;
            for (int dy = 0; dy < K; ++dy) {
                for (int dx = 0; dx < K; ++dx) {
                    const float* pg = prev + ((gy + dy - md) * WW + (gx + dx - md)) * CC;
                    float d = 0.0f;
                    for (int c = 0; c < CC; c += 4) {
                        const float4 pv = __ldg((const float4*)(pg + c));
                        const float4 qv = __ldg((const float4*)(qp + c));
                        d = dist4(qv, pv, d);
                        if (d >= m) break;
                    }
                    if (d < m) m = d;
                }
            }
            best[u] = m;
        }
        float* op = out + (gy * WW + gx) * nobj;
        for (int t = 0; t < no; t++) op[t] = best[t];
        for (int t = no; t < nobj; t++) op[t] = 1.0f;  // unreachable in practice
    }
}

extern "C" void kernel_launch(void* const* d_in, const int* in_sizes, int n_in,
                              void* d_out, int out_size) {
    // metadata order: prev_frame_embedding, query_embedding, prev_frame_labels,
    //                 gt_ids, max_distance
    const float* prev   = (const float*)d_in[0];
    const float* query  = (const float*)d_in[1];
    const int*   labels = (const int*)d_in[2];
    const int*   gt     = (const int*)d_in[3];
    const int*   mdp    = (n_in >= 5) ? (const int*)d_in[4] : nullptr;
    const int    nobj   = in_sizes[3];

    dim3 grid(WW / TX, HH / TY);   // 16 x 16 = 256 CTAs
    IntVOS_27015344292341_kernel<<<grid, NTHREADS>>>(
        prev, query, labels, gt, mdp, (float*)d_out, nobj);
}

// round 10
// speedup vs baseline: 1.0060x; 1.0060x over previous
#include <cuda_runtime.h>

// Problem constants (fixed by the dataset: H=W=128, C=100).
#define HH 128
#define WW 128
#define CC 100          // channels; CC % 4 == 0 so float4 loads stay 16B-aligned
#define TY 8            // tile rows per CTA
#define TX 8            // tile cols per CTA
#define MDMAX 15        // fast path supports max_distance <= 15
#define PWS (TX + 2*MDMAX)   // 38: padded halo stride (sized for MDMAX)
#define MAXOBJ 4        // fast path supports n_obj <= 4 (dataset has 3)
#define NTHREADS 256    // 64 pixels * 4 dy-chunk threads

__device__ __forceinline__ float dist4(float4 q, float4 p, float d) {
    float t0 = q.x - p.x, t1 = q.y - p.y, t2 = q.z - p.z, t3 = q.w - p.w;
    d = fmaf(t0, t0, d);
    d = fmaf(t1, t1, d);
    d = fmaf(t2, t2, d);
    d = fmaf(t3, t3, d);
    return d;
}

__global__ __launch_bounds__(NTHREADS)
void IntVOS_27015344292341_kernel(const float* __restrict__ prev,
                                  const float* __restrict__ query,
                                  const int*   __restrict__ labels,
                                  const int*   __restrict__ gt,
                                  const int*   __restrict__ mdp,
                                  float*       __restrict__ out,
                                  int nobj)
{
    const int md = mdp ? mdp[0] : MDMAX;
    const int K  = 2 * md + 1;

    const int tid   = threadIdx.x;
    const int tileX = blockIdx.x * TX;
    const int tileY = blockIdx.y * TY;
    const int lane  = tid & 31;
    const unsigned grpmask = 0xFu << (lane & ~3);   // the 4 lanes of this pixel

    const int pix   = tid >> 2;          // 0..63 pixel within tile
    const int chunk = tid & 3;           // dy-range chunk 0..3
    const int py = pix / TX, px = pix - (pix / TX) * TX;
    const int gy = tileY + py, gx = tileX + px;
    const float* qp = query + (gy * WW + gx) * CC;

    const int dy0 = (chunk * K) >> 2;
    const int dy1 = ((chunk + 1) * K) >> 2;

    if (md <= MDMAX && nobj <= MAXOBJ) {
        // ---------------- fast path ----------------
        __shared__ float4        smA[PWS * PWS];   // channels 0..3
        __shared__ float4        smB[PWS * PWS];   // channels 4..7
        __shared__ unsigned char smObj[PWS * PWS]; // matched object id or 255
        __shared__ int           sgt[MAXOBJ];

        if (tid < MAXOBJ) sgt[tid] = (tid < nobj) ? gt[tid] : 0;
        __syncthreads();

        // Load halo: object index + first 8 channels of prev embedding.
        const int PW = TX + 2 * md;
        for (int i = tid; i < PW * PW; i += NTHREADS) {
            const int sy = i / PW, sx = i - sy * PW;
            const int hy = tileY + sy - md, hx = tileX + sx - md;
            int o = 255;
            float4 a = make_float4(0.f, 0.f, 0.f, 0.f), b = a;
            if (hy >= 0 && hy < HH && hx >= 0 && hx < WW) {
                const int lab = labels[hy * WW + hx];
                #pragma unroll
                for (int t = 0; t < MAXOBJ; t++)
                    if (t < nobj && sgt[t] == lab) o = t;
                const float4* pp = (const float4*)(prev + (hy * WW + hx) * CC);
                a = pp[0];
                b = pp[1];
            }
            const int si = sy * PWS + sx;
            smA[si] = a;
            smB[si] = b;
            smObj[si] = (unsigned char)o;
        }
        __syncthreads();

        const float4 qa = ((const float4*)qp)[0];
        const float4 qb = ((const float4*)qp)[1];

        float best[MAXOBJ];
        #pragma unroll
        for (int t = 0; t < MAXOBJ; t++) best[t] = 1.0f;  // clamp folded into init
        int u = -1;     // the single object seen so far (for all-match detection)
        int allm = 1;   // window entirely matches one object?

        for (int dy = dy0; dy < dy1; ++dy) {
            const int base = (py + dy) * PWS + px;
            const float* prow = prev + ((gy + dy - md) * WW + (gx - md)) * CC;
            for (int dx = 0; dx < K; ++dx) {
                const int o = (int)smObj[base + dx];
                if (o == 255) { allm = 0; continue; }      // OOB or label matches no gt id
                if (u < 0) u = o; else if (o != u) allm = 0;

                float b = 1.0f;
                #pragma unroll
                for (int t = 0; t < MAXOBJ; t++) if (o == t) b = best[t];

                // Stage 1: channels 0..3 from shared. Partial sums are monotone
                // (non-negative fp32 adds), so partial >= b  =>  full d >= b: exact skip.
                float d = dist4(qa, smA[base + dx], 0.0f);
                if (d < b) {
                    // Stage 2: channels 4..7 from shared.
                    d = dist4(qb, smB[base + dx], d);
                    if (d < b) {
                        // Rare tail: channels 8..99 from global (L2-resident).
                        const float* pg = prow + dx * CC;
                        #pragma unroll 1
                        for (int c = 8; c < CC; c += 4) {
                            const float4 pv = __ldg((const float4*)(pg + c));
                            const float4 qv = __ldg((const float4*)(qp + c));
                            d = dist4(qv, pv, d);
                            if (d >= b) break;
                        }
                        if (d < b) {
                            #pragma unroll
                            for (int t = 0; t < MAXOBJ; t++) if (o == t) best[t] = d;
                        }
                    }
                }
            }
        }

        // Combine the 4 dy-chunk lanes of this pixel (all lanes converged here).
        #pragma unroll
        for (int t = 0; t < MAXOBJ; t++) {
            best[t] = fminf(best[t], __shfl_xor_sync(0xffffffffu, best[t], 1));
            best[t] = fminf(best[t], __shfl_xor_sync(0xffffffffu, best[t], 2));
        }
        {
            int am2 = __shfl_xor_sync(0xffffffffu, allm, 1);
            int u2  = __shfl_xor_sync(0xffffffffu, u, 1);
            allm = allm & am2 & ((u < 0 || u2 < 0 || u == u2) ? 1 : 0);
            u = (u < 0) ? u2 : u;
            am2 = __shfl_xor_sync(0xffffffffu, allm, 2);
            u2  = __shfl_xor_sync(0xffffffffu, u, 2);
            allm = allm & am2 & ((u < 0 || u2 < 0 || u == u2) ? 1 : 0);
            u = (u < 0) ? u2 : u;
        }

        if (allm && u >= 0) {
            // Every offset in the window matched object u: the reference takes the
            // UNCLAMPED min over full distances. Recompute exactly (extremely rare).
            float m = 3.402823466e38f;
            for (int dy = dy0; dy < dy1; ++dy) {
                for (int dx = 0; dx < K; ++dx) {
                    const float* pg = prev + ((gy + dy - md) * WW + (gx + dx - md)) * CC;
                    float d = 0.0f;
                    #pragma unroll 1
                    for (int c = 0; c < CC; c += 4) {
                        const float4 pv = __ldg((const float4*)(pg + c));
                        const float4 qv = __ldg((const float4*)(qp + c));
                        d = dist4(qv, pv, d);
                        if (d >= m) break;   // exact: partial >= m => full >= m
                    }
                    if (d < m) m = d;
                }
            }
            m = fminf(m, __shfl_xor_sync(grpmask, m, 1));
            m = fminf(m, __shfl_xor_sync(grpmask, m, 2));
            #pragma unroll
            for (int t = 0; t < MAXOBJ; t++) if (u == t) best[t] = m;
        }

        if (chunk == 0) {
            float* op = out + (gy * WW + gx) * nobj;
            #pragma unroll
            for (int t = 0; t < MAXOBJ; t++)
                if (t < nobj) op[t] = best[t];
        }
    } else {
        // ---------------- generic fallback (md > 15 or nobj > 4) ----------------
        if (chunk != 0) return;           // one thread per pixel; perf irrelevant
        const int NB = 32;
        float best[NB];
        const int no = (nobj < NB) ? nobj : NB;
        for (int t = 0; t < no; t++) best[t] = 1.0f;
        int u = -1, allm = 1;

        for (int dy = 0; dy < K; ++dy) {
            for (int dx = 0; dx < K; ++dx) {
                const int ny = gy + dy - md, nx = gx + dx - md;
                if (ny < 0 || ny >= HH || nx < 0 || nx >= WW) { allm = 0; continue; }
                const int lab = labels[ny * WW + nx];
                int o = -1;
                for (int t = 0; t < no; t++) if (__ldg(gt + t) == lab) o = t;
                if (o < 0) { allm = 0; continue; }
                if (u < 0) u = o; else if (o != u) allm = 0;
                const float b = best[o];
                const float* pg = prev + (ny * WW + nx) * CC;
                float d = 0.0f;
                for (int c = 0; c < CC; c += 4) {
                    const float4 pv = __ldg((const float4*)(pg + c));
                    const float4 qv = __ldg((const float4*)(qp + c));
                    d = dist4(qv, pv, d);
                    if (d >= b) break;
                }
                if (d < b) best[o] = d;
            }
        }
        if (allm && u >= 0) {
            float m = 3.402823466e38f;
            for (int dy = 0; dy < K; ++dy) {
                for (int dx = 0; dx < K; ++dx) {
                    const float* pg = prev + ((gy + dy - md) * WW + (gx + dx - md)) * CC;
                    float d = 0.0f;
                    for (int c = 0; c < CC; c += 4) {
                        const float4 pv = __ldg((const float4*)(pg + c));
                        const float4 qv = __ldg((const float4*)(qp + c));
                        d = dist4(qv, pv, d);
                        if (d >= m) break;
                    }
                    if (d < m) m = d;
                }
            }
            best[u] = m;
        }
        float* op = out + (gy * WW + gx) * nobj;
        for (int t = 0; t < no; t++) op[t] = best[t];
        for (int t = no; t < nobj; t++) op[t] = 1.0f;  // unreachable in practice
    }
}

extern "C" void kernel_launch(void* const* d_in, const int* in_sizes, int n_in,
                              void* d_out, int out_size) {
    // metadata order: prev_frame_embedding, query_embedding, prev_frame_labels,
    //                 gt_ids, max_distance
    const float* prev   = (const float*)d_in[0];
    const float* query  = (const float*)d_in[1];
    const int*   labels = (const int*)d_in[2];
    const int*   gt     = (const int*)d_in[3];
    const int*   mdp    = (n_in >= 5) ? (const int*)d_in[4] : nullptr;
    const int    nobj   = in_sizes[3];

    dim3 grid(WW / TX, HH / TY);   // 16 x 16 = 256 CTAs
    IntVOS_27015344292341_kernel<<<grid, NTHREADS>>>(
        prev, query, labels, gt, mdp, (float*)d_out, nobj);
}

// round 11
// speedup vs baseline: 1.9929x; 1.9811x over previous
#include <cuda_runtime.h>

// Problem constants (fixed by the dataset: H=W=128, C=100).
#define HH 128
#define WW 128
#define CC 100
#define TY 8
#define TX 8
#define MDMAX 15
#define PWMAX (TX + 2*MDMAX)    // 38: max halo width
#define PWS 39                  // padded halo stride (odd -> conflict-free LDS across chunk rows)
#define MAXOBJ 4
#define NTHREADS 512            // 64 pixels * 8 dy-interleaved chunks
#define NCHUNK 8

// ---- dynamic shared memory layout (bytes) ----
#define SMA_OFF   0                          // neg prev ch0..3, float4[PWS*PWS]
#define SMB_OFF   (PWS*PWS*16)               // neg prev ch4..7, float4[PWS*PWS]
#define SOBJ_OFF  (2*PWS*PWS*16)             // object id / 255, u8[PWS*PWS]
#define SROWU_OFF (SOBJ_OFF + PWS*PWS)       // row-uniformity table, u8[PWMAX*TX]
#define SGT_OFF   ((SROWU_OFF + PWMAX*TX + 15) & ~15)
#define SMEM_BYTES (SGT_OFF + MAXOBJ*4)

// ---- packed f32x2 helpers (sm_103a) ----
__device__ __forceinline__ unsigned long long f2_add(unsigned long long a, unsigned long long b) {
    unsigned long long r; asm("add.rn.f32x2 %0, %1, %2;" : "=l"(r) : "l"(a), "l"(b)); return r;
}
__device__ __forceinline__ unsigned long long f2_mul(unsigned long long a, unsigned long long b) {
    unsigned long long r; asm("mul.rn.f32x2 %0, %1, %2;" : "=l"(r) : "l"(a), "l"(b)); return r;
}
__device__ __forceinline__ unsigned long long f2_fma(unsigned long long a, unsigned long long b,
                                                     unsigned long long c) {
    unsigned long long r; asm("fma.rn.f32x2 %0, %1, %2, %3;" : "=l"(r) : "l"(a), "l"(b), "l"(c)); return r;
}
__device__ __forceinline__ float f2_hsum(unsigned long long v) {
    float lo, hi; asm("mov.b64 {%0, %1}, %2;" : "=f"(lo), "=f"(hi) : "l"(v)); return lo + hi;
}

__device__ __forceinline__ float dist4s(float4 q, float4 p, float d) {
    float t0 = q.x - p.x, t1 = q.y - p.y, t2 = q.z - p.z, t3 = q.w - p.w;
    d = fmaf(t0, t0, d); d = fmaf(t1, t1, d); d = fmaf(t2, t2, d); d = fmaf(t3, t3, d);
    return d;
}

// KC = compile-time K (31) or 0 => use runtime Krt.
template <int KC>
__device__ __forceinline__ void fast_body(
    const float* __restrict__ prev, const float* __restrict__ query,
    const int* __restrict__ labels, const int* __restrict__ gt,
    float* __restrict__ out, int nobj, int md, int Krt,
    unsigned char* smraw)
{
    const int K  = KC ? KC : Krt;
    const int PW = TX + 2 * md;

    ulonglong2*    smA   = (ulonglong2*)(smraw + SMA_OFF);
    ulonglong2*    smB   = (ulonglong2*)(smraw + SMB_OFF);
    unsigned char* smObj = smraw + SOBJ_OFF;
    unsigned char* rowU  = smraw + SROWU_OFF;
    int*           sgt   = (int*)(smraw + SGT_OFF);

    const int tid   = threadIdx.x;
    const int tileX = blockIdx.x * TX;
    const int tileY = blockIdx.y * TY;

    if (tid < MAXOBJ) sgt[tid] = (tid < nobj) ? gt[tid] : 0x7fffffff;
    __syncthreads();

    // ---- halo load: object id + NEGATED first 8 channels of prev embedding ----
    for (int i = tid; i < PW * PW; i += NTHREADS) {
        const int sy = i / PW, sx = i - sy * PW;
        const int hy = tileY + sy - md, hx = tileX + sx - md;
        int o = 255;
        float4 a = make_float4(0.f, 0.f, 0.f, 0.f), b = a;
        if (hy >= 0 && hy < HH && hx >= 0 && hx < WW) {
            const int lab = labels[hy * WW + hx];
            #pragma unroll
            for (int t = 0; t < MAXOBJ; t++) if (sgt[t] == lab) o = t;
            const float4* pp = (const float4*)(prev + (hy * WW + hx) * CC);
            const float4 a0 = pp[0], b0 = pp[1];
            a = make_float4(-a0.x, -a0.y, -a0.z, -a0.w);
            b = make_float4(-b0.x, -b0.y, -b0.z, -b0.w);
        }
        const int si = sy * PWS + sx;
        ((float4*)smA)[si] = a;
        ((float4*)smB)[si] = b;
        smObj[si] = (unsigned char)o;
    }
    __syncthreads();

    // ---- rowU: per (halo row, pixel col): uniform object over [px, px+K) or 255 ----
    if (tid < PW * TX) {
        const int sy = tid >> 3, px = tid & 7;
        const unsigned char* r = smObj + sy * PWS + px;
        int v = r[0];
        for (int j = 1; j < K; j++) if ((int)r[j] != v) v = 255;
        rowU[tid] = (unsigned char)v;
    }
    __syncthreads();

    const int pix = tid >> 3, chunk = tid & 7;      // 8 interleaved dy-chunks per pixel
    const int py = pix >> 3, px = pix & 7;
    const int gy = tileY + py, gx = tileX + px;
    const float* qp = query + (gy * WW + gx) * CC;
    const ulonglong2 qA = ((const ulonglong2*)qp)[0];   // q ch0..3 packed
    const ulonglong2 qB = ((const ulonglong2*)qp)[1];   // q ch4..7 packed

    float best[MAXOBJ];
    #pragma unroll
    for (int t = 0; t < MAXOBJ; t++) best[t] = (t < nobj) ? 1.0f : 0.0f;
    float th = 1.0f;   // = max_t best[t]; skipping d >= th is exact for every object
    int v = -1;        // uniform-window object (from rowU); -1 none seen, 255 broken

    for (int i = 0; i < 4; i++) {
        const int dy = chunk + 8 * i;               // stride-8 interleave
        if (dy >= K) break;
        {   // window-uniformity bookkeeping, once per row
            const int rv = rowU[(py + dy) * TX + px];
            v = (v == -1) ? rv : ((v == rv) ? v : 255);
        }
        const int base = (py + dy) * PWS + px;
        const float* prow = prev + ((gy + dy - md) * WW + (gx - md)) * CC;
        for (int dx = 0; dx < K; dx++) {
            // stage 1: channels 0..3 (packed), no object logic
            const ulonglong2 p = smA[base + dx];
            const unsigned long long t01 = f2_add(qA.x, p.x);
            unsigned long long acc = f2_mul(t01, t01);
            const unsigned long long t23 = f2_add(qA.y, p.y);
            acc = f2_fma(t23, t23, acc);
            const float d4 = f2_hsum(acc);
            if (d4 < th) {
                // stage 2: channels 4..7 (packed), still vs th only
                const ulonglong2 p2 = smB[base + dx];
                const unsigned long long t45 = f2_add(qB.x, p2.x);
                acc = f2_fma(t45, t45, acc);
                const unsigned long long t67 = f2_add(qB.y, p2.y);
                acc = f2_fma(t67, t67, acc);
                const float d8 = f2_hsum(acc);
                if (d8 < th) {
                    // stage 3 (rare): resolve object, exact threshold, global tail
                    const int o = (int)smObj[base + dx];
                    if (o != 255) {
                        float b = 1.0f;
                        #pragma unroll
                        for (int t = 0; t < MAXOBJ; t++) if (o == t) b = best[t];
                        if (d8 < b) {
                            const float* pg = prow + dx * CC;
                            float d = d8;
                            #pragma unroll 1
                            for (int c = 8; c < CC; c += 4) {
                                const float4 pv = __ldg((const float4*)(pg + c));
                                const float4 qv = __ldg((const float4*)(qp + c));
                                d = dist4s(qv, pv, d);
                                if (d >= b) break;       // monotone partial: exact skip
                            }
                            if (d < b) {
                                #pragma unroll
                                for (int t = 0; t < MAXOBJ; t++) if (o == t) best[t] = d;
                                th = fmaxf(fmaxf(best[0], best[1]), fmaxf(best[2], best[3]));
                            }
                        }
                    }
                }
            }
        }
    }

    // ---- combine the 8 chunk lanes of each pixel ----
    #pragma unroll
    for (int t = 0; t < MAXOBJ; t++) {
        best[t] = fminf(best[t], __shfl_xor_sync(0xffffffffu, best[t], 1));
        best[t] = fminf(best[t], __shfl_xor_sync(0xffffffffu, best[t], 2));
        best[t] = fminf(best[t], __shfl_xor_sync(0xffffffffu, best[t], 4));
    }
    #pragma unroll
    for (int s = 1; s <= 4; s <<= 1) {
        const int v2 = __shfl_xor_sync(0xffffffffu, v, s);
        v = (v == -1) ? v2 : ((v2 == -1 || v2 == v) ? v : 255);
    }

    if (v >= 0 && v < MAXOBJ) {
        // Entire K x K window matched object v: reference min is UNCLAMPED.
        // Recompute exactly (astronomically rare; perf irrelevant).
        const int lane = tid & 31;
        const unsigned gmask = 0xFFu << (lane & 24);   // this pixel's 8 lanes
        float m = 3.402823466e38f;
        for (int i = 0; i < 4; i++) {
            const int dy = chunk + 8 * i;
            if (dy >= K) break;
            for (int dx = 0; dx < K; dx++) {
                const float* pg = prev + ((gy + dy - md) * WW + (gx + dx - md)) * CC;
                float d = 0.0f;
                #pragma unroll 1
                for (int c = 0; c < CC; c += 4) {
                    const float4 pv = __ldg((const float4*)(pg + c));
                    const float4 qv = __ldg((const float4*)(qp + c));
                    d = dist4s(qv, pv, d);
                    if (d >= m) break;
                }
                if (d < m) m = d;
            }
        }
        m = fminf(m, __shfl_xor_sync(gmask, m, 1));
        m = fminf(m, __shfl_xor_sync(gmask, m, 2));
        m = fminf(m, __shfl_xor_sync(gmask, m, 4));
        #pragma unroll
        for (int t = 0; t < MAXOBJ; t++) if (v == t) best[t] = m;
    }

    if (chunk == 0) {
        float* op = out + (gy * WW + gx) * nobj;
        #pragma unroll
        for (int t = 0; t < MAXOBJ; t++)
            if (t < nobj) op[t] = best[t];
    }
}

__global__ __launch_bounds__(NTHREADS, 2)
void IntVOS_27015344292341_kernel(const float* __restrict__ prev,
                                  const float* __restrict__ query,
                                  const int*   __restrict__ labels,
                                  const int*   __restrict__ gt,
                                  const int*   __restrict__ mdp,
                                  float*       __restrict__ out,
                                  int nobj)
{
    extern __shared__ unsigned char smraw[];
    const int md = mdp ? mdp[0] : MDMAX;
    const int K  = 2 * md + 1;

    if (md <= MDMAX && nobj <= MAXOBJ && nobj > 0) {
        if (md == MDMAX)
            fast_body<2 * MDMAX + 1>(prev, query, labels, gt, out, nobj, md, K, smraw);
        else
            fast_body<0>(prev, query, labels, gt, out, nobj, md, K, smraw);
        return;
    }

    // ---------------- generic fallback (md > 15 or nobj > 4): one thread/pixel ----------------
    const int tid = threadIdx.x;
    if (tid >= TY * TX) return;
    const int py = tid >> 3, px = tid & 7;
    const int gy = blockIdx.y * TY + py, gx = blockIdx.x * TX + px;
    const float* qp = query + (gy * WW + gx) * CC;

    const int NB = 32;
    float best[NB];
    const int no = (nobj < NB) ? nobj : NB;
    for (int t = 0; t < no; t++) best[t] = 1.0f;
    int u = -1, allm = 1;

    for (int dy = 0; dy < K; ++dy) {
        for (int dx = 0; dx < K; ++dx) {
            const int ny = gy + dy - md, nx = gx + dx - md;
            if (ny < 0 || ny >= HH || nx < 0 || nx >= WW) { allm = 0; continue; }
            const int lab = labels[ny * WW + nx];
            int o = -1;
            for (int t = 0; t < no; t++) if (__ldg(gt + t) == lab) o = t;
            if (o < 0) { allm = 0; continue; }
            if (u < 0) u = o; else if (o != u) allm = 0;
            const float b = best[o];
            const float* pg = prev + (ny * WW + nx) * CC;
            float d = 0.0f;
            for (int c = 0; c < CC; c += 4) {
                const float4 pv = __ldg((const float4*)(pg + c));
                const float4 qv = __ldg((const float4*)(qp + c));
                d = dist4s(qv, pv, d);
                if (d >= b) break;
            }
            if (d < b) best[o] = d;
        }
    }
    if (allm && u >= 0) {
        float m = 3.402823466e38f;
        for (int dy = 0; dy < K; ++dy) {
            for (int dx = 0; dx < K; ++dx) {
                const float* pg = prev + ((gy + dy - md) * WW + (gx + dx - md)) * CC;
                float d = 0.0f;
                for (int c = 0; c < CC; c += 4) {
                    const float4 pv = __ldg((const float4*)(pg + c));
                    const float4 qv = __ldg((const float4*)(qp + c));
                    d = dist4s(qv, pv, d);
                    if (d >= m) break;
                }
                if (d < m) m = d;
            }
        }
        best[u] = m;
    }
    float* op = out + (gy * WW + gx) * nobj;
    for (int t = 0; t < no; t++) op[t] = best[t];
    for (int t = no; t < nobj; t++) op[t] = 1.0f;
}

extern "C" void kernel_launch(void* const* d_in, const int* in_sizes, int n_in,
                              void* d_out, int out_size) {
    // metadata order: prev_frame_embedding, query_embedding, prev_frame_labels,
    //                 gt_ids, max_distance
    const float* prev   = (const float*)d_in[0];
    const float* query  = (const float*)d_in[1];
    const int*   labels = (const int*)d_in[2];
    const int*   gt     = (const int*)d_in[3];
    const int*   mdp    = (n_in >= 5) ? (const int*)d_in[4] : nullptr;
    const int    nobj   = in_sizes[3];

    cudaFuncSetAttribute(IntVOS_27015344292341_kernel,
                         cudaFuncAttributeMaxDynamicSharedMemorySize, SMEM_BYTES);

    dim3 grid(WW / TX, HH / TY);   // 16 x 16 = 256 CTAs
    IntVOS_27015344292341_kernel<<<grid, NTHREADS, SMEM_BYTES>>>(
        prev, query, labels, gt, mdp, (float*)d_out, nobj);
}